// round 15
// baseline (speedup 1.0000x reference)
#include <cuda_runtime.h>
#include <math.h>
#include <stdint.h>

#define NTHR  256
#define MELB  125                       // mel: 125 blocks * 2048 quads = 256000 quads
#define DCBLK 120                       // dc: 120 blocks * 256 thr = 30720 rows (1 thr/row)
#define NBLK  (MELB + DCBLK + 2)        // 247; last 2 = stop blocks

// problem shape (fixed by setup_inputs)
#define Bc    16
#define Tc    800
#define NMELc 80
#define Nc    3
#define Hc    4
#define Sc    160
#define Kc    5                         // Tc / Sc
#define NM4   20                        // NMELc / 4
#define MQ    2048                      // quads per mel block
#define MBYTES (MQ * 16)                // 32768 bytes per array per block
#define SMEM_DYN (2 * MBYTES + 512)

__device__ double g_mel, g_dc, g_stop;
__device__ int g_mask_cnt;
__device__ unsigned long long g_len_sum;
__device__ unsigned int g_done;

__device__ __forceinline__ uint32_t smem_u32(const void* p) {
    return (uint32_t)__cvta_generic_to_shared(p);
}

__global__ __launch_bounds__(NTHR)
void loss_kernel(const int* __restrict__ lengths,
                 const int* __restrict__ mask,          // JAX bool -> int32
                 const float* __restrict__ stop_pred,
                 const float* __restrict__ mels_pred,
                 const float* __restrict__ mels_target,
                 const float* __restrict__ align,
                 float* __restrict__ out)
{
    extern __shared__ char dsm[];
    float4* s_pred = (float4*)dsm;
    float4* s_tgt  = (float4*)(dsm + MBYTES);
    float*  s_maskv = (float*)(dsm + 2 * MBYTES);                 // 112 floats
    unsigned long long* s_mbar = (unsigned long long*)(dsm + 2 * MBYTES + 448);
    float*  s_red  = (float*)(dsm + 2 * MBYTES + 456);            // 8 floats

    const int tid  = threadIdx.x;
    const int bid  = blockIdx.x;
    const int lane = tid & 31;
    const int warp = tid >> 5;

    if (bid < MELB) {
        // ---- mel L1 via cp.async.bulk: 2 x 32KB engine copies per block ----
        const int Q0     = bid * MQ;
        const int base_m = Q0 / NM4;
        const uint32_t mb = smem_u32(s_mbar);

        if (tid == 0)
            asm volatile("mbarrier.init.shared.b64 [%0], 1;" :: "r"(mb) : "memory");
        if (tid < 104) {                      // stage mask values for this block
            int mi = base_m + tid;
            if (mi > Bc * Tc - 1) mi = Bc * Tc - 1;
            s_maskv[tid] = __ldg(&mask[mi]) ? 1.0f : 0.0f;
        }
        __syncthreads();                      // mbar init + mask visible

        if (tid == 0) {
            asm volatile("mbarrier.arrive.expect_tx.shared.b64 _, [%0], %1;"
                         :: "r"(mb), "r"(2 * MBYTES) : "memory");
            asm volatile("cp.async.bulk.shared::cta.global.mbarrier::complete_tx::bytes"
                         " [%0], [%1], %2, [%3];"
                         :: "r"(smem_u32(s_pred)),
                            "l"(mels_pred + (size_t)Q0 * 4), "r"(MBYTES), "r"(mb)
                         : "memory");
            asm volatile("cp.async.bulk.shared::cta.global.mbarrier::complete_tx::bytes"
                         " [%0], [%1], %2, [%3];"
                         :: "r"(smem_u32(s_tgt)),
                            "l"(mels_target + (size_t)Q0 * 4), "r"(MBYTES), "r"(mb)
                         : "memory");
        }
        asm volatile(
            "{\n\t.reg .pred P;\n"
            "W%=:\n\t"
            "mbarrier.try_wait.parity.acquire.cta.shared::cta.b64 P, [%0], 0, 0x989680;\n\t"
            "@P bra D%=;\n\t"
            "bra W%=;\n"
            "D%=:\n\t}"
            :: "r"(mb) : "memory");

        float acc = 0.0f;
        #pragma unroll
        for (int j = 0; j < 8; j++) {
            const int ql = tid + j * NTHR;               // conflict-free LDS.128
            float4 p = s_pred[ql];
            float4 g = s_tgt[ql];
            float  m = s_maskv[(unsigned)(Q0 + ql) / NM4 - base_m];
            acc += fabsf(fmaf(p.x, m, -g.x)) + fabsf(fmaf(p.y, m, -g.y))
                 + fabsf(fmaf(p.z, m, -g.z)) + fabsf(fmaf(p.w, m, -g.w));
        }
        #pragma unroll
        for (int o = 16; o; o >>= 1) acc += __shfl_xor_sync(0xffffffffu, acc, o);
        if (lane == 0) s_red[warp] = acc;
        __syncthreads();
        if (tid == 0) {
            float tm = 0.0f;
            #pragma unroll
            for (int i = 0; i < NTHR / 32; i++) tm += s_red[i];
            atomicAdd(&g_mel, (double)tm);
        }
    } else if (bid < MELB + DCBLK) {
        // ---- dc band sum: ONE thread per (n,bh,s) row; window <= 20 floats
        //      -> at most 6 float4 quads, predicated + edge-selected ----
        const int r     = (bid - MELB) * NTHR + tid;
        const int s     = r % Sc;
        const int plane = r / Sc;
        const int b     = (plane % (Bc * Hc)) % Bc;    // reshape (n,H,B): b = bh % B
        float acc = 0.0f;
        if (Tc >= __ldg(&lengths[b])) {                 // bmask
            const int t_lo = (s >= 50) ? ((s - 50) / Kc + 1) : 0;   // s < k*t+50
            int t_hi = (s + 50) / Kc + 1;                            // k*t-50 <= s
            if (t_hi > Tc) t_hi = Tc;
            const int q_lo = t_lo >> 2;
            const int q_hi = (t_hi + 3) >> 2;
            const float4* row = (const float4*)(align + (size_t)r * Tc);
            float4 v[6];
            #pragma unroll
            for (int j = 0; j < 6; j++) {
                const int qq = q_lo + j;
                v[j] = (qq < q_hi) ? __ldg(&row[qq]) : make_float4(0.f,0.f,0.f,0.f);
            }
            #pragma unroll
            for (int j = 0; j < 6; j++) {
                const int t0 = (q_lo + j) << 2;
                acc += ((t0     >= t_lo && t0     < t_hi) ? v[j].x : 0.0f)
                     + ((t0 + 1 >= t_lo && t0 + 1 < t_hi) ? v[j].y : 0.0f)
                     + ((t0 + 2 >= t_lo && t0 + 2 < t_hi) ? v[j].z : 0.0f)
                     + ((t0 + 3 >= t_lo && t0 + 3 < t_hi) ? v[j].w : 0.0f);
            }
        }
        #pragma unroll
        for (int o = 16; o; o >>= 1) acc += __shfl_xor_sync(0xffffffffu, acc, o);
        if (lane == 0) s_red[warp] = acc;
        __syncthreads();
        if (tid == 0) {
            float td = 0.0f;
            #pragma unroll
            for (int i = 0; i < NTHR / 32; i++) td += s_red[i];
            atomicAdd(&g_dc, (double)td);
        }
    } else {
        // ---- stop BCE: one warp per batch row (last 2 blocks) ----
        const int b = (bid - MELB - DCBLK) * (NTHR / 32) + warp;   // 0..15
        if (b < Bc) {
            int cnt = 0, maxi = -1;
            const int* mrow = mask + b * Tc;
            #pragma unroll 5
            for (int t = lane; t < Tc; t += 32)
                if (mrow[t]) { cnt++; maxi = t; }       // t increasing: lane-max = last true
            #pragma unroll
            for (int o = 16; o; o >>= 1) {
                cnt += __shfl_xor_sync(0xffffffffu, cnt, o);
                int m2 = __shfl_xor_sync(0xffffffffu, maxi, o);
                maxi = max(maxi, m2);
            }
            if (lane == 0) {
                atomicAdd(&g_mask_cnt, cnt);
                const int idx = (maxi < 0) ? 0 : maxi;
                float lg = logf(stop_pred[b * Tc + idx]);
                if (lg < -100.0f) lg = -100.0f;
                atomicAdd(&g_stop, (double)(-5.0f * lg));   // STOP_WEIGHT = 5
                __threadfence();   // writer fences its own atomics (pre-done-count)
            }
        }
        if (bid == MELB + DCBLK && tid == 0) {
            unsigned long long ls = 0;
            #pragma unroll
            for (int b2 = 0; b2 < Bc; b2++) ls += (unsigned long long)__ldg(&lengths[b2]);
            atomicAdd(&g_len_sum, ls);
        }
        __syncthreads();   // stop writers' fences done before tid0 counts this block
    }

    // ---- lean epilogue: ONLY tid 0 (the global writer) participates ----
    if (tid == 0) {
        __threadfence();                         // order own atomic before done-count
        unsigned int prev = atomicAdd(&g_done, 1u);
        if (prev == NBLK - 1) {
            // all blocks' adds performed at L2; read through L2, not atomics
            double mel = __ldcg(&g_mel);
            double dc  = __ldcg(&g_dc);
            double st  = __ldcg(&g_stop);
            int    mc  = __ldcg(&g_mask_cnt);
            unsigned long long ls = __ldcg(&g_len_sum);

            double mel_loss  = mel / ((double)Bc * (double)Tc * (double)NMELc);
            double stop_loss = st / (double)mc;
            double dcv = dc / ((double)Hc * (double)ls * (double)Nc);
            out[0] = (float)(mel_loss + stop_loss - 1e-4 * dcv);  // DC_STRENGTH = 1e-4

            g_mel = 0.0; g_dc = 0.0; g_stop = 0.0;
            g_mask_cnt = 0; g_len_sum = 0ull; g_done = 0u;
            __threadfence();
        }
    }
}

extern "C" void kernel_launch(void* const* d_in, const int* in_sizes, int n_in,
                              void* d_out, int out_size)
{
    const int*   lengths     = (const int*)d_in[0];
    const int*   mask        = (const int*)d_in[1];     // bool -> int32
    const float* stop_pred   = (const float*)d_in[2];
    const float* mels_pred   = (const float*)d_in[3];
    const float* mels_target = (const float*)d_in[4];
    const float* align       = (const float*)d_in[5];

    static int attr_done = 0;
    if (!attr_done) {   // capture-time only; free at replay
        cudaFuncSetAttribute(loss_kernel,
                             cudaFuncAttributeMaxDynamicSharedMemorySize, SMEM_DYN);
        attr_done = 1;
    }
    loss_kernel<<<NBLK, NTHR, SMEM_DYN>>>(lengths, mask, stop_pred, mels_pred,
                                          mels_target, align, (float*)d_out);
}